// round 14
// baseline (speedup 1.0000x reference)
#include <cuda_runtime.h>
#include <cuda_bf16.h>
#include <math.h>
#include <cstdint>

// Shapes (fixed): B=8, L=1024, D=512, H=8, dh=64
//
//   K1a: Q = x @ Wq
//   k_mid: fused { K,V = x @ {Wk,Wv} } + { R2[bh] = Q_head @ Wet^T } (1:8)
//   K3: tensorized flash attention, logits = 0.125 * (q.k) * R2[l,|l-s|]
//
// This round: mma issue reordered term-major so same-accumulator re-hits are
// >= 8-16 instructions apart (was 2-4) -> hide HMMA writeback latency.

// ---------------- scratch (device globals; no allocations) ----------------
static __device__ float g_R2[67108864];                 // [B*H][1024][1024]

static __device__ __nv_bfloat16 g_xh[8192 * 512], g_xl[8192 * 512];
static __device__ __nv_bfloat16 g_Wth[3 * 512 * 512], g_Wtl[3 * 512 * 512];   // Wt[z][n][k]
static __device__ __nv_bfloat16 g_Weth[1024 * 64], g_Wetl[1024 * 64];         // Wet[n][k]
static __device__ __nv_bfloat16 g_Qh[8192 * 512], g_Ql[8192 * 512];
static __device__ __nv_bfloat16 g_Kh[8192 * 512], g_Kl[8192 * 512];
static __device__ __nv_bfloat16 g_Vh[8192 * 512], g_Vl[8192 * 512];

// ---------------- PTX helpers (baseline sm_80-era PTX only) ----------------
__device__ __forceinline__ uint32_t smem_u32(const void* p) {
    uint32_t a;
    asm("{ .reg .u64 t; cvta.to.shared.u64 t, %1; cvt.u32.u64 %0, t; }" : "=r"(a) : "l"(p));
    return a;
}
__device__ __forceinline__ void ldm_x4(uint32_t a[4], uint32_t addr) {
    asm volatile("ldmatrix.sync.aligned.m8n8.x4.shared.b16 {%0,%1,%2,%3}, [%4];"
                 : "=r"(a[0]), "=r"(a[1]), "=r"(a[2]), "=r"(a[3]) : "r"(addr));
}
__device__ __forceinline__ void ldm_x4_t(uint32_t a[4], uint32_t addr) {
    asm volatile("ldmatrix.sync.aligned.m8n8.x4.trans.shared.b16 {%0,%1,%2,%3}, [%4];"
                 : "=r"(a[0]), "=r"(a[1]), "=r"(a[2]), "=r"(a[3]) : "r"(addr));
}
__device__ __forceinline__ void mma_bf16(float c[4], const uint32_t a[4],
                                         uint32_t b0, uint32_t b1) {
    asm volatile(
        "mma.sync.aligned.m16n8k16.row.col.f32.bf16.bf16.f32 "
        "{%0,%1,%2,%3}, {%4,%5,%6,%7}, {%8,%9}, {%0,%1,%2,%3};"
        : "+f"(c[0]), "+f"(c[1]), "+f"(c[2]), "+f"(c[3])
        : "r"(a[0]), "r"(a[1]), "r"(a[2]), "r"(a[3]), "r"(b0), "r"(b1));
}
__device__ __forceinline__ void cp_async16(uint32_t dst, const void* src) {
    asm volatile("cp.async.cg.shared.global [%0], [%1], 16;" :: "r"(dst), "l"(src) : "memory");
}
#define CP_COMMIT() asm volatile("cp.async.commit_group;" ::: "memory")
#define CP_WAIT0()  asm volatile("cp.async.wait_group 0;" ::: "memory")
#define CP_WAIT1()  asm volatile("cp.async.wait_group 1;" ::: "memory")
#define CP_WAIT2()  asm volatile("cp.async.wait_group 2;" ::: "memory")

__device__ __forceinline__ uint32_t pack_bf16(float x, float y) {
    __nv_bfloat162 t(__float2bfloat16(x), __float2bfloat16(y));
    return *(uint32_t*)&t;
}
__device__ __forceinline__ float bhi(float v) {
    return __bfloat162float(__float2bfloat16(v));
}

// ---------------- GEMM smem tile geometry (128 x 32 bf16, stride 80 B) -----
static constexpr int TROW = 80;
static constexpr int TBYTES = 128 * TROW;   // 10240
static constexpr int BUF = 4 * TBYTES;      // 40960

__device__ __forceinline__ void issue_tile(uint32_t sdst, const __nv_bfloat16* __restrict__ g,
                                           long rstride, int tid) {
#pragma unroll
    for (int r = 0; r < 2; r++) {
        int idx = tid * 2 + r;
        int row = idx >> 2, c = idx & 3;
        cp_async16(sdst + row * TROW + c * 16, g + (long)row * rstride + c * 16 / 2);
    }
}

// Term-major mma order: same accumulator re-hit distance = 16 instructions.
__device__ __forceinline__ void compute32(uint32_t sAh, uint32_t sAl,
                                          uint32_t sBh, uint32_t sBl,
                                          float acc[2][8][4], int mw, int nw, int lid) {
#pragma unroll
    for (int ks = 0; ks < 2; ks++) {
        const int acol2 = (ks * 16 + ((lid >> 4) << 3)) * 2;
        const int arow  = mw + (lid & 15);
        uint32_t A0[4], A1[4], L0[4], L1[4];
        ldm_x4(A0, sAh + arow * TROW + acol2);
        ldm_x4(A1, sAh + (arow + 16) * TROW + acol2);
        ldm_x4(L0, sAl + arow * TROW + acol2);
        ldm_x4(L1, sAl + (arow + 16) * TROW + acol2);

        const int bcol2 = (ks * 16 + (((lid >> 3) & 1) << 3)) * 2;
        const int brow  = nw + (lid & 7) + (((lid >> 4) & 1) << 3);
        uint32_t BH[4][4];
#pragma unroll
        for (int p = 0; p < 4; p++) ldm_x4(BH[p], sBh + (brow + p * 16) * TROW + bcol2);

#pragma unroll
        for (int p = 0; p < 4; p++) {
            mma_bf16(acc[0][2 * p], A0, BH[p][0], BH[p][1]);
            mma_bf16(acc[0][2 * p + 1], A0, BH[p][2], BH[p][3]);
        }
#pragma unroll
        for (int p = 0; p < 4; p++) {
            mma_bf16(acc[1][2 * p], A1, BH[p][0], BH[p][1]);
            mma_bf16(acc[1][2 * p + 1], A1, BH[p][2], BH[p][3]);
        }
#pragma unroll
        for (int p = 0; p < 4; p++) {
            mma_bf16(acc[0][2 * p], L0, BH[p][0], BH[p][1]);
            mma_bf16(acc[0][2 * p + 1], L0, BH[p][2], BH[p][3]);
        }
#pragma unroll
        for (int p = 0; p < 4; p++) {
            mma_bf16(acc[1][2 * p], L1, BH[p][0], BH[p][1]);
            mma_bf16(acc[1][2 * p + 1], L1, BH[p][2], BH[p][3]);
        }

        uint32_t BL[4][4];
#pragma unroll
        for (int p = 0; p < 4; p++) ldm_x4(BL[p], sBl + (brow + p * 16) * TROW + bcol2);
#pragma unroll
        for (int p = 0; p < 4; p++) {
            mma_bf16(acc[0][2 * p], A0, BL[p][0], BL[p][1]);
            mma_bf16(acc[0][2 * p + 1], A0, BL[p][2], BL[p][3]);
        }
#pragma unroll
        for (int p = 0; p < 4; p++) {
            mma_bf16(acc[1][2 * p], A1, BL[p][0], BL[p][1]);
            mma_bf16(acc[1][2 * p + 1], A1, BL[p][2], BL[p][3]);
        }
    }
}

// ---------------- conversion pre-kernels ----------------
__global__ void k_split_x(const float* __restrict__ src) {
    int i = (blockIdx.x * 256 + threadIdx.x) * 4;
    float4 v = *(const float4*)(src + i);
    __nv_bfloat16 h0 = __float2bfloat16(v.x), h1 = __float2bfloat16(v.y);
    __nv_bfloat16 h2 = __float2bfloat16(v.z), h3 = __float2bfloat16(v.w);
    *(__nv_bfloat162*)(g_xh + i)     = __nv_bfloat162(h0, h1);
    *(__nv_bfloat162*)(g_xh + i + 2) = __nv_bfloat162(h2, h3);
    *(__nv_bfloat162*)(g_xl + i)     = __nv_bfloat162(
        __float2bfloat16(v.x - __bfloat162float(h0)), __float2bfloat16(v.y - __bfloat162float(h1)));
    *(__nv_bfloat162*)(g_xl + i + 2) = __nv_bfloat162(
        __float2bfloat16(v.z - __bfloat162float(h2)), __float2bfloat16(v.w - __bfloat162float(h3)));
}

__global__ void k_wsplit(const float* __restrict__ Wq, const float* __restrict__ Wk,
                         const float* __restrict__ Wv) {
    __shared__ float t[32][33];
    const int z = blockIdx.z;
    const float* __restrict__ W = (z == 0) ? Wq : (z == 1) ? Wk : Wv;
    const int n0 = blockIdx.x * 32, k0 = blockIdx.y * 32;
    const int tx = threadIdx.x, ty = threadIdx.y;
#pragma unroll
    for (int i = 0; i < 32; i += 8)
        t[ty + i][tx] = W[(size_t)(k0 + ty + i) * 512 + n0 + tx];
    __syncthreads();
#pragma unroll
    for (int i = 0; i < 32; i += 8) {
        float v = t[tx][ty + i];
        __nv_bfloat16 h = __float2bfloat16(v);
        size_t o = (size_t)z * 262144 + (size_t)(n0 + ty + i) * 512 + k0 + tx;
        g_Wth[o] = h;
        g_Wtl[o] = __float2bfloat16(v - __bfloat162float(h));
    }
}

__global__ void k_wesplit(const float* __restrict__ We) {
    int id = blockIdx.x * 256 + threadIdx.x;
    int n = id >> 6, k = id & 63;
    float v = We[(size_t)k * 1024 + (1023 - n)];
    __nv_bfloat16 h = __float2bfloat16(v);
    g_Weth[id] = h;
    g_Wetl[id] = __float2bfloat16(v - __bfloat162float(h));
}

// ---------------------------------------------------------------------------
// Body: one 128x128 tile of {Q,K,V} = x @ W_z. Epilogue: bf16 hi/lo splits.
// ---------------------------------------------------------------------------
__device__ void qkv_body(char* dsm, int tid, int n0, int m0, int z) {
    const uint32_t sb0 = smem_u32(dsm);
    const int lid = tid & 31, wid = tid >> 5;
    const int mw = (wid & 3) * 32, nw = (wid >> 2) * 64;

    const __nv_bfloat16* Ah = g_xh + (size_t)m0 * 512;
    const __nv_bfloat16* Al = g_xl + (size_t)m0 * 512;
    const __nv_bfloat16* Bh = g_Wth + (size_t)z * 262144 + (size_t)n0 * 512;
    const __nv_bfloat16* Bl = g_Wtl + (size_t)z * 262144 + (size_t)n0 * 512;

    float acc[2][8][4];
#pragma unroll
    for (int i = 0; i < 2; i++)
#pragma unroll
        for (int j = 0; j < 8; j++)
#pragma unroll
            for (int c = 0; c < 4; c++) acc[i][j][c] = 0.f;

#pragma unroll
    for (int t = 0; t < 2; t++) {
        const uint32_t sb = sb0 + t * BUF;
        issue_tile(sb + 0 * TBYTES, Ah + t * 32, 512, tid);
        issue_tile(sb + 1 * TBYTES, Al + t * 32, 512, tid);
        issue_tile(sb + 2 * TBYTES, Bh + t * 32, 512, tid);
        issue_tile(sb + 3 * TBYTES, Bl + t * 32, 512, tid);
        CP_COMMIT();
    }

    const int KT = 16;
    for (int kt = 0; kt < KT; kt++) {
        if (kt < KT - 1) CP_WAIT1(); else CP_WAIT0();
        __syncthreads();
        const uint32_t sb = sb0 + (kt & 1) * BUF;
        compute32(sb, sb + TBYTES, sb + 2 * TBYTES, sb + 3 * TBYTES, acc, mw, nw, lid);
        __syncthreads();
        if (kt + 2 < KT) {
            const int t = kt + 2;
            issue_tile(sb + 0 * TBYTES, Ah + t * 32, 512, tid);
            issue_tile(sb + 1 * TBYTES, Al + t * 32, 512, tid);
            issue_tile(sb + 2 * TBYTES, Bh + t * 32, 512, tid);
            issue_tile(sb + 3 * TBYTES, Bl + t * 32, 512, tid);
            CP_COMMIT();
        }
    }

    __nv_bfloat16* __restrict__ Ho = (z == 0) ? g_Qh : (z == 1) ? g_Kh : g_Vh;
    __nv_bfloat16* __restrict__ Lo = (z == 0) ? g_Ql : (z == 1) ? g_Kl : g_Vl;
#pragma unroll
    for (int mt = 0; mt < 2; mt++)
#pragma unroll
        for (int nt = 0; nt < 8; nt++) {
            const float* c = acc[mt][nt];
            const int m = m0 + mw + mt * 16 + (lid >> 2);
            const int n = n0 + nw + (nt >> 1) * 16 + (nt & 1) * 8 + (lid & 3) * 2;
            float h0 = bhi(c[0]), h1 = bhi(c[1]), h2 = bhi(c[2]), h3 = bhi(c[3]);
            *(uint32_t*)&Ho[(size_t)m * 512 + n]       = pack_bf16(h0, h1);
            *(uint32_t*)&Lo[(size_t)m * 512 + n]       = pack_bf16(c[0] - h0, c[1] - h1);
            *(uint32_t*)&Ho[(size_t)(m + 8) * 512 + n] = pack_bf16(h2, h3);
            *(uint32_t*)&Lo[(size_t)(m + 8) * 512 + n] = pack_bf16(c[2] - h2, c[3] - h3);
        }
}

// ---------------------------------------------------------------------------
// Body: one 128x128 tile of R2[bh] = Q_head @ Wet^T.  K=64.
// ---------------------------------------------------------------------------
__device__ void rel_body(char* dsm, int tid, int n0, int m0, int bh) {
    const uint32_t sb0 = smem_u32(dsm);
    const int lid = tid & 31, wid = tid >> 5;
    const int mw = (wid & 3) * 32, nw = (wid >> 2) * 64;
    const int b = bh >> 3, h = bh & 7;

    const __nv_bfloat16* Ah = g_Qh + (size_t)(b * 1024 + m0) * 512 + h * 64;
    const __nv_bfloat16* Al = g_Ql + (size_t)(b * 1024 + m0) * 512 + h * 64;
    const __nv_bfloat16* Bh = g_Weth + (size_t)n0 * 64;
    const __nv_bfloat16* Bl = g_Wetl + (size_t)n0 * 64;

    float acc[2][8][4];
#pragma unroll
    for (int i = 0; i < 2; i++)
#pragma unroll
        for (int j = 0; j < 8; j++)
#pragma unroll
            for (int c = 0; c < 4; c++) acc[i][j][c] = 0.f;

#pragma unroll
    for (int t = 0; t < 2; t++) {
        const uint32_t sb = sb0 + t * BUF;
        issue_tile(sb + 0 * TBYTES, Ah + t * 32, 512, tid);
        issue_tile(sb + 1 * TBYTES, Al + t * 32, 512, tid);
        issue_tile(sb + 2 * TBYTES, Bh + t * 32, 64, tid);
        issue_tile(sb + 3 * TBYTES, Bl + t * 32, 64, tid);
        CP_COMMIT();
    }

#pragma unroll
    for (int kt = 0; kt < 2; kt++) {
        if (kt == 0) CP_WAIT1(); else CP_WAIT0();
        __syncthreads();
        const uint32_t sb = sb0 + kt * BUF;
        compute32(sb, sb + TBYTES, sb + 2 * TBYTES, sb + 3 * TBYTES, acc, mw, nw, lid);
        __syncthreads();
    }

    float* __restrict__ C = g_R2 + (size_t)bh * 1048576;
#pragma unroll
    for (int mt = 0; mt < 2; mt++)
#pragma unroll
        for (int nt = 0; nt < 8; nt++) {
            const float* c = acc[mt][nt];
            const int m = m0 + mw + mt * 16 + (lid >> 2);
            const int n = n0 + nw + (nt >> 1) * 16 + (nt & 1) * 8 + (lid & 3) * 2;
            *(float2*)&C[(size_t)m * 1024 + n]       = make_float2(c[0], c[1]);
            *(float2*)&C[(size_t)(m + 8) * 1024 + n] = make_float2(c[2], c[3]);
        }
}

// ---------------------------------------------------------------------------
// K1a: z=0 only (produces Q splits needed by K2).
// ---------------------------------------------------------------------------
__global__ __launch_bounds__(256, 2) void k_qkv0() {
    extern __shared__ __align__(16) char dsm[];
    qkv_body(dsm, threadIdx.x, blockIdx.x * 128, blockIdx.y * 128, 0);
}

// ---------------------------------------------------------------------------
// k_mid: fused K1b (z=1,2; 512 CTAs) + K2 (4096 CTAs), interleaved 1:8.
// K2 skips tiles with n0 > max(m0+127, 1023-m0) (never read by K3).
// ---------------------------------------------------------------------------
__global__ __launch_bounds__(256, 2) void k_mid() {
    extern __shared__ __align__(16) char dsm[];
    const int id = blockIdx.z * 64 + blockIdx.y * 8 + blockIdx.x;   // [0, 4608)
    const int q = id / 9, r = id - q * 9;
    if (r == 8) {
        const int n0 = (q & 3) * 128;
        const int m0 = ((q >> 2) & 63) * 128;
        const int z  = 1 + (q >> 8);
        qkv_body(dsm, threadIdx.x, n0, m0, z);
    } else {
        const int k2 = id - q;            // [0, 4096), bijective
        const int bh = k2 >> 6;
        const int rem = k2 & 63;
        const int m0 = (rem >> 3) * 128;
        const int n0 = (rem & 7) * 128;
        const int mx = (m0 + 127 > 1023 - m0) ? (m0 + 127) : (1023 - m0);
        if (n0 > mx) return;
        rel_body(dsm, threadIdx.x, n0, m0, bh);
    }
}

// ---------------------------------------------------------------------------
// K3: tensorized flash attention (256 threads), term-major mma order.
// ---------------------------------------------------------------------------
static constexpr int SROW = 144;                    // 128B data + 16 pad
static constexpr int QMAT = 128 * SROW;             // 18432
static constexpr int KVMAT = 64 * SROW;             // 9216
static constexpr int KVBUF = 4 * KVMAT;             // 36864
static constexpr int SMEM_ATT = 2 * QMAT + 2 * KVBUF;   // 110592

__device__ __forceinline__ void issue_q128(uint32_t s, const __nv_bfloat16* __restrict__ g, int tid) {
#pragma unroll
    for (int i = 0; i < 4; i++) {
        int idx = tid * 4 + i;                 // 0..1023
        int row = idx >> 3, c = idx & 7;
        cp_async16(s + row * SROW + c * 16, g + (size_t)row * 512 + c * 8);
    }
}
__device__ __forceinline__ void issue_kv64(uint32_t s, const __nv_bfloat16* __restrict__ g, int tid) {
#pragma unroll
    for (int i = 0; i < 2; i++) {
        int idx = tid * 2 + i;                 // 0..511
        int row = idx >> 3, c = idx & 7;
        cp_async16(s + row * SROW + c * 16, g + (size_t)row * 512 + c * 8);
    }
}

__global__ __launch_bounds__(256) void k_attn_mma(float* __restrict__ out) {
    extern __shared__ __align__(16) char dsm[];
    const uint32_t sb = smem_u32(dsm);
    const uint32_t sQh = sb, sQl = sb + QMAT;
    const uint32_t sBuf = sb + 2 * QMAT;

    const int tid = threadIdx.x, lid = tid & 31, wid = tid >> 5;
    const int l0 = blockIdx.x * 128, h = blockIdx.y, b = blockIdx.z;

    const size_t rowoff = (size_t)(b * 1024) * 512 + h * 64;
    const __nv_bfloat16* Qhg = g_Qh + rowoff + (size_t)l0 * 512;
    const __nv_bfloat16* Qlg = g_Ql + rowoff + (size_t)l0 * 512;
    const __nv_bfloat16* Khg = g_Kh + rowoff;
    const __nv_bfloat16* Klg = g_Kl + rowoff;
    const __nv_bfloat16* Vhg = g_Vh + rowoff;
    const __nv_bfloat16* Vlg = g_Vl + rowoff;
    const float* __restrict__ R = g_R2 + (size_t)(b * 8 + h) * 1048576;

    issue_q128(sQh, Qhg, tid);
    issue_q128(sQl, Qlg, tid);
    CP_COMMIT();
#pragma unroll
    for (int t = 0; t < 2; t++) {
        const uint32_t Bt = sBuf + t * KVBUF;
        issue_kv64(Bt,             Khg + (size_t)t * 64 * 512, tid);
        issue_kv64(Bt + KVMAT,     Klg + (size_t)t * 64 * 512, tid);
        issue_kv64(Bt + 2 * KVMAT, Vhg + (size_t)t * 64 * 512, tid);
        issue_kv64(Bt + 3 * KVMAT, Vlg + (size_t)t * 64 * 512, tid);
        CP_COMMIT();
    }
    CP_WAIT2();
    __syncthreads();

    uint32_t QH[4][4], QL[4][4];
    {
        const int aoff = (16 * wid + (lid & 15)) * SROW;
#pragma unroll
        for (int ks = 0; ks < 4; ks++) {
            const int c2 = (ks * 16 + ((lid >> 4) << 3)) * 2;
            ldm_x4(QH[ks], sQh + aoff + c2);
            ldm_x4(QL[ks], sQl + aoff + c2);
        }
    }

    float O[8][4];
#pragma unroll
    for (int t = 0; t < 8; t++)
#pragma unroll
        for (int j = 0; j < 4; j++) O[t][j] = 0.f;
    float m0f = -INFINITY, m1f = -INFINITY, r0f = 0.f, r1f = 0.f;

    const int r0 = lid >> 2, c2i = (lid & 3) * 2;
    const int lA = l0 + 16 * wid + r0, lB = lA + 8;
    const float* RA = R + (size_t)lA * 1024;
    const float* RB = R + (size_t)lB * 1024;

    for (int kt = 0; kt < 16; kt++) {
        if (kt < 15) CP_WAIT1(); else CP_WAIT0();
        __syncthreads();
        const uint32_t Bt = sBuf + (kt & 1) * KVBUF;
        const uint32_t bKh = Bt, bKl = Bt + KVMAT, bVh = Bt + 2 * KVMAT, bVl = Bt + 3 * KVMAT;

        // ---- S = Q @ K^T, term-major (same-acc distance = 8) ----
        float S[8][4];
#pragma unroll
        for (int t = 0; t < 8; t++)
#pragma unroll
            for (int j = 0; j < 4; j++) S[t][j] = 0.f;

#pragma unroll
        for (int ks = 0; ks < 4; ks++) {
            const int bc2 = (ks * 16 + (((lid >> 3) & 1) << 3)) * 2;
            const int br  = (lid & 7) + (((lid >> 4) & 1) << 3);
            uint32_t KH[4][4];
#pragma unroll
            for (int p = 0; p < 4; p++) ldm_x4(KH[p], bKh + (p * 16 + br) * SROW + bc2);
#pragma unroll
            for (int p = 0; p < 4; p++) {
                mma_bf16(S[2 * p],     QH[ks], KH[p][0], KH[p][1]);
                mma_bf16(S[2 * p + 1], QH[ks], KH[p][2], KH[p][3]);
            }
#pragma unroll
            for (int p = 0; p < 4; p++) {
                mma_bf16(S[2 * p],     QL[ks], KH[p][0], KH[p][1]);
                mma_bf16(S[2 * p + 1], QL[ks], KH[p][2], KH[p][3]);
            }
            uint32_t KL[4][4];
#pragma unroll
            for (int p = 0; p < 4; p++) ldm_x4(KL[p], bKl + (p * 16 + br) * SROW + bc2);
#pragma unroll
            for (int p = 0; p < 4; p++) {
                mma_bf16(S[2 * p],     QH[ks], KL[p][0], KL[p][1]);
                mma_bf16(S[2 * p + 1], QH[ks], KL[p][2], KL[p][3]);
            }
        }

        const int s0 = kt * 64;
        float mx0 = -INFINITY, mx1 = -INFINITY;
#pragma unroll
        for (int t = 0; t < 8; t++) {
            const int sc = s0 + t * 8 + c2i;
            int dA0 = lA - sc;     dA0 = (dA0 < 0) ? -dA0 : dA0;
            int dA1 = lA - sc - 1; dA1 = (dA1 < 0) ? -dA1 : dA1;
            int dB0 = lB - sc;     dB0 = (dB0 < 0) ? -dB0 : dB0;
            int dB1 = lB - sc - 1; dB1 = (dB1 < 0) ? -dB1 : dB1;
            S[t][0] = 0.125f * S[t][0] * RA[dA0];
            S[t][1] = 0.125f * S[t][1] * RA[dA1];
            S[t][2] = 0.125f * S[t][2] * RB[dB0];
            S[t][3] = 0.125f * S[t][3] * RB[dB1];
            mx0 = fmaxf(mx0, fmaxf(S[t][0], S[t][1]));
            mx1 = fmaxf(mx1, fmaxf(S[t][2], S[t][3]));
        }
        mx0 = fmaxf(mx0, __shfl_xor_sync(0xffffffffu, mx0, 1));
        mx0 = fmaxf(mx0, __shfl_xor_sync(0xffffffffu, mx0, 2));
        mx1 = fmaxf(mx1, __shfl_xor_sync(0xffffffffu, mx1, 1));
        mx1 = fmaxf(mx1, __shfl_xor_sync(0xffffffffu, mx1, 2));

        const float mn0 = fmaxf(m0f, mx0), mn1 = fmaxf(m1f, mx1);
        const float al0 = __expf(m0f - mn0), al1 = __expf(m1f - mn1);
        m0f = mn0; m1f = mn1;

        float sum0 = 0.f, sum1 = 0.f;
        uint32_t PH[4][4], PL[4][4];
#pragma unroll
        for (int q = 0; q < 4; q++) {
#pragma unroll
            for (int u = 0; u < 2; u++) {
                const int t = 2 * q + u;
                float e0 = __expf(S[t][0] - mn0);
                float e1 = __expf(S[t][1] - mn0);
                float e2 = __expf(S[t][2] - mn1);
                float e3 = __expf(S[t][3] - mn1);
                sum0 += e0 + e1;
                sum1 += e2 + e3;
                float h0 = bhi(e0), h1 = bhi(e1), h2 = bhi(e2), h3 = bhi(e3);
                PH[q][2 * u]     = pack_bf16(h0, h1);
                PH[q][2 * u + 1] = pack_bf16(h2, h3);
                PL[q][2 * u]     = pack_bf16(e0 - h0, e1 - h1);
                PL[q][2 * u + 1] = pack_bf16(e2 - h2, e3 - h3);
            }
        }
        sum0 += __shfl_xor_sync(0xffffffffu, sum0, 1);
        sum0 += __shfl_xor_sync(0xffffffffu, sum0, 2);
        sum1 += __shfl_xor_sync(0xffffffffu, sum1, 1);
        sum1 += __shfl_xor_sync(0xffffffffu, sum1, 2);
        r0f = r0f * al0 + sum0;
        r1f = r1f * al1 + sum1;

#pragma unroll
        for (int t = 0; t < 8; t++) {
            O[t][0] *= al0; O[t][1] *= al0;
            O[t][2] *= al1; O[t][3] *= al1;
        }

        // ---- O += P @ V, term-major (same-acc distance = 8) ----
#pragma unroll
        for (int q = 0; q < 4; q++) {
            const int vrb = q * 16 + (lid & 7) + (((lid >> 3) & 1) << 3);
            const int vc2 = (((lid >> 4) & 1) << 3) * 2;
            uint32_t VH[4][4];
#pragma unroll
            for (int p = 0; p < 4; p++) ldm_x4_t(VH[p], bVh + vrb * SROW + p * 32 + vc2);
#pragma unroll
            for (int p = 0; p < 4; p++) {
                mma_bf16(O[2 * p],     PH[q], VH[p][0], VH[p][1]);
                mma_bf16(O[2 * p + 1], PH[q], VH[p][2], VH[p][3]);
            }
#pragma unroll
            for (int p = 0; p < 4; p++) {
                mma_bf16(O[2 * p],     PL[q], VH[p][0], VH[p][1]);
                mma_bf16(O[2 * p + 1], PL[q], VH[p][2], VH[p][3]);
            }
            uint32_t VL[4][4];
#pragma unroll
            for (int p = 0; p < 4; p++) ldm_x4_t(VL[p], bVl + vrb * SROW + p * 32 + vc2);
#pragma unroll
            for (int p = 0; p < 4; p++) {
                mma_bf16(O[2 * p],     PH[q], VL[p][0], VL[p][1]);
                mma_bf16(O[2 * p + 1], PH[q], VL[p][2], VL[p][3]);
            }
        }
        __syncthreads();

        if (kt + 2 < 16) {
            const int t = kt + 2;
            issue_kv64(Bt,             Khg + (size_t)t * 64 * 512, tid);
            issue_kv64(Bt + KVMAT,     Klg + (size_t)t * 64 * 512, tid);
            issue_kv64(Bt + 2 * KVMAT, Vhg + (size_t)t * 64 * 512, tid);
            issue_kv64(Bt + 3 * KVMAT, Vlg + (size_t)t * 64 * 512, tid);
            CP_COMMIT();
        }
    }

    const float inv0 = 1.f / r0f, inv1 = 1.f / r1f;
    float* __restrict__ oA = out + (size_t)(b * 1024 + lA) * 512 + h * 64;
    float* __restrict__ oB = out + (size_t)(b * 1024 + lB) * 512 + h * 64;
#pragma unroll
    for (int t = 0; t < 8; t++) {
        const int d = t * 8 + c2i;
        *(float2*)(oA + d) = make_float2(O[t][0] * inv0, O[t][1] * inv0);
        *(float2*)(oB + d) = make_float2(O[t][2] * inv1, O[t][3] * inv1);
    }
}

// ---------------------------------------------------------------------------

extern "C" void kernel_launch(void* const* d_in, const int* in_sizes, int n_in,
                              void* d_out, int out_size)
{
    (void)in_sizes; (void)n_in; (void)out_size;
    const float* x  = (const float*)d_in[0];
    const float* Wq = (const float*)d_in[1];
    const float* Wk = (const float*)d_in[2];
    const float* Wv = (const float*)d_in[3];
    const float* We = (const float*)d_in[4];
    float* out = (float*)d_out;

    const int SMEM_MMA = 2 * BUF;   // 81920
    cudaFuncSetAttribute(k_qkv0, cudaFuncAttributeMaxDynamicSharedMemorySize, SMEM_MMA);
    cudaFuncSetAttribute(k_mid, cudaFuncAttributeMaxDynamicSharedMemorySize, SMEM_MMA);
    cudaFuncSetAttribute(k_attn_mma, cudaFuncAttributeMaxDynamicSharedMemorySize, SMEM_ATT);

    k_split_x<<<4096, 256>>>(x);
    k_wsplit<<<dim3(16, 16, 3), dim3(32, 8)>>>(Wq, Wk, Wv);
    k_wesplit<<<256, 256>>>(We);
    k_qkv0<<<dim3(4, 64, 1), 256, SMEM_MMA>>>();
    k_mid<<<dim3(8, 8, 72), 256, SMEM_MMA>>>();
    k_attn_mma<<<dim3(8, 8, 8), 256, SMEM_ATT>>>(out);
}

// round 15
// speedup vs baseline: 1.0659x; 1.0659x over previous
#include <cuda_runtime.h>
#include <cuda_bf16.h>
#include <math.h>
#include <cstdint>

// Shapes (fixed): B=8, L=1024, D=512, H=8, dh=64
//
//   k_qkv0: Q = x @ Wq
//   k_mid:  compacted fused { K,V = x @ {Wk,Wv} : 512 tiles } +
//           { R2[bh] = Q_head @ Wet^T : 3328 live tiles } interleaved 1:6.5
//   K3: tensorized flash attention with R2-gather prefetched one iteration
//       ahead (LDG latency hidden under softmax+PV+next S-mma).

// ---------------- scratch (device globals; no allocations) ----------------
static __device__ float g_R2[67108864];                 // [B*H][1024][1024]

static __device__ __nv_bfloat16 g_xh[8192 * 512], g_xl[8192 * 512];
static __device__ __nv_bfloat16 g_Wth[3 * 512 * 512], g_Wtl[3 * 512 * 512];   // Wt[z][n][k]
static __device__ __nv_bfloat16 g_Weth[1024 * 64], g_Wetl[1024 * 64];         // Wet[n][k]
static __device__ __nv_bfloat16 g_Qh[8192 * 512], g_Ql[8192 * 512];
static __device__ __nv_bfloat16 g_Kh[8192 * 512], g_Kl[8192 * 512];
static __device__ __nv_bfloat16 g_Vh[8192 * 512], g_Vl[8192 * 512];

// ---------------- PTX helpers (baseline sm_80-era PTX only) ----------------
__device__ __forceinline__ uint32_t smem_u32(const void* p) {
    uint32_t a;
    asm("{ .reg .u64 t; cvta.to.shared.u64 t, %1; cvt.u32.u64 %0, t; }" : "=r"(a) : "l"(p));
    return a;
}
__device__ __forceinline__ void ldm_x4(uint32_t a[4], uint32_t addr) {
    asm volatile("ldmatrix.sync.aligned.m8n8.x4.shared.b16 {%0,%1,%2,%3}, [%4];"
                 : "=r"(a[0]), "=r"(a[1]), "=r"(a[2]), "=r"(a[3]) : "r"(addr));
}
__device__ __forceinline__ void ldm_x4_t(uint32_t a[4], uint32_t addr) {
    asm volatile("ldmatrix.sync.aligned.m8n8.x4.trans.shared.b16 {%0,%1,%2,%3}, [%4];"
                 : "=r"(a[0]), "=r"(a[1]), "=r"(a[2]), "=r"(a[3]) : "r"(addr));
}
__device__ __forceinline__ void mma_bf16(float c[4], const uint32_t a[4],
                                         uint32_t b0, uint32_t b1) {
    asm volatile(
        "mma.sync.aligned.m16n8k16.row.col.f32.bf16.bf16.f32 "
        "{%0,%1,%2,%3}, {%4,%5,%6,%7}, {%8,%9}, {%0,%1,%2,%3};"
        : "+f"(c[0]), "+f"(c[1]), "+f"(c[2]), "+f"(c[3])
        : "r"(a[0]), "r"(a[1]), "r"(a[2]), "r"(a[3]), "r"(b0), "r"(b1));
}
__device__ __forceinline__ void cp_async16(uint32_t dst, const void* src) {
    asm volatile("cp.async.cg.shared.global [%0], [%1], 16;" :: "r"(dst), "l"(src) : "memory");
}
#define CP_COMMIT() asm volatile("cp.async.commit_group;" ::: "memory")
#define CP_WAIT0()  asm volatile("cp.async.wait_group 0;" ::: "memory")
#define CP_WAIT1()  asm volatile("cp.async.wait_group 1;" ::: "memory")
#define CP_WAIT2()  asm volatile("cp.async.wait_group 2;" ::: "memory")

__device__ __forceinline__ uint32_t pack_bf16(float x, float y) {
    __nv_bfloat162 t(__float2bfloat16(x), __float2bfloat16(y));
    return *(uint32_t*)&t;
}
__device__ __forceinline__ float bhi(float v) {
    return __bfloat162float(__float2bfloat16(v));
}

// ---------------- GEMM smem tile geometry (128 x 32 bf16, stride 80 B) -----
static constexpr int TROW = 80;
static constexpr int TBYTES = 128 * TROW;   // 10240
static constexpr int BUF = 4 * TBYTES;      // 40960

__device__ __forceinline__ void issue_tile(uint32_t sdst, const __nv_bfloat16* __restrict__ g,
                                           long rstride, int tid) {
#pragma unroll
    for (int r = 0; r < 2; r++) {
        int idx = tid * 2 + r;
        int row = idx >> 2, c = idx & 3;
        cp_async16(sdst + row * TROW + c * 16, g + (long)row * rstride + c * 8);
    }
}

__device__ __forceinline__ void compute32(uint32_t sAh, uint32_t sAl,
                                          uint32_t sBh, uint32_t sBl,
                                          float acc[2][8][4], int mw, int nw, int lid) {
#pragma unroll
    for (int ks = 0; ks < 2; ks++) {
        const int acol2 = (ks * 16 + ((lid >> 4) << 3)) * 2;
        const int arow  = mw + (lid & 15);
        uint32_t A0[4], A1[4], L0[4], L1[4];
        ldm_x4(A0, sAh + arow * TROW + acol2);
        ldm_x4(A1, sAh + (arow + 16) * TROW + acol2);
        ldm_x4(L0, sAl + arow * TROW + acol2);
        ldm_x4(L1, sAl + (arow + 16) * TROW + acol2);

        const int bcol2 = (ks * 16 + (((lid >> 3) & 1) << 3)) * 2;
        const int brow  = nw + (lid & 7) + (((lid >> 4) & 1) << 3);
        uint32_t Bx[4][4];
#pragma unroll
        for (int p = 0; p < 4; p++) ldm_x4(Bx[p], sBh + (brow + p * 16) * TROW + bcol2);
#pragma unroll
        for (int p = 0; p < 4; p++) {
            mma_bf16(acc[0][2 * p],     A0, Bx[p][0], Bx[p][1]);
            mma_bf16(acc[0][2 * p + 1], A0, Bx[p][2], Bx[p][3]);
            mma_bf16(acc[1][2 * p],     A1, Bx[p][0], Bx[p][1]);
            mma_bf16(acc[1][2 * p + 1], A1, Bx[p][2], Bx[p][3]);
            mma_bf16(acc[0][2 * p],     L0, Bx[p][0], Bx[p][1]);
            mma_bf16(acc[0][2 * p + 1], L0, Bx[p][2], Bx[p][3]);
            mma_bf16(acc[1][2 * p],     L1, Bx[p][0], Bx[p][1]);
            mma_bf16(acc[1][2 * p + 1], L1, Bx[p][2], Bx[p][3]);
        }
#pragma unroll
        for (int p = 0; p < 4; p++) ldm_x4(Bx[p], sBl + (brow + p * 16) * TROW + bcol2);
#pragma unroll
        for (int p = 0; p < 4; p++) {
            mma_bf16(acc[0][2 * p],     A0, Bx[p][0], Bx[p][1]);
            mma_bf16(acc[0][2 * p + 1], A0, Bx[p][2], Bx[p][3]);
            mma_bf16(acc[1][2 * p],     A1, Bx[p][0], Bx[p][1]);
            mma_bf16(acc[1][2 * p + 1], A1, Bx[p][2], Bx[p][3]);
        }
    }
}

// ---------------- conversion pre-kernels ----------------
__global__ void k_split_x(const float* __restrict__ src) {
    int i = (blockIdx.x * 256 + threadIdx.x) * 4;
    float4 v = *(const float4*)(src + i);
    __nv_bfloat16 h0 = __float2bfloat16(v.x), h1 = __float2bfloat16(v.y);
    __nv_bfloat16 h2 = __float2bfloat16(v.z), h3 = __float2bfloat16(v.w);
    *(__nv_bfloat162*)(g_xh + i)     = __nv_bfloat162(h0, h1);
    *(__nv_bfloat162*)(g_xh + i + 2) = __nv_bfloat162(h2, h3);
    *(__nv_bfloat162*)(g_xl + i)     = __nv_bfloat162(
        __float2bfloat16(v.x - __bfloat162float(h0)), __float2bfloat16(v.y - __bfloat162float(h1)));
    *(__nv_bfloat162*)(g_xl + i + 2) = __nv_bfloat162(
        __float2bfloat16(v.z - __bfloat162float(h2)), __float2bfloat16(v.w - __bfloat162float(h3)));
}

__global__ void k_wsplit(const float* __restrict__ Wq, const float* __restrict__ Wk,
                         const float* __restrict__ Wv) {
    __shared__ float t[32][33];
    const int z = blockIdx.z;
    const float* __restrict__ W = (z == 0) ? Wq : (z == 1) ? Wk : Wv;
    const int n0 = blockIdx.x * 32, k0 = blockIdx.y * 32;
    const int tx = threadIdx.x, ty = threadIdx.y;
#pragma unroll
    for (int i = 0; i < 32; i += 8)
        t[ty + i][tx] = W[(size_t)(k0 + ty + i) * 512 + n0 + tx];
    __syncthreads();
#pragma unroll
    for (int i = 0; i < 32; i += 8) {
        float v = t[tx][ty + i];
        __nv_bfloat16 h = __float2bfloat16(v);
        size_t o = (size_t)z * 262144 + (size_t)(n0 + ty + i) * 512 + k0 + tx;
        g_Wth[o] = h;
        g_Wtl[o] = __float2bfloat16(v - __bfloat162float(h));
    }
}

__global__ void k_wesplit(const float* __restrict__ We) {
    int id = blockIdx.x * 256 + threadIdx.x;
    int n = id >> 6, k = id & 63;
    float v = We[(size_t)k * 1024 + (1023 - n)];
    __nv_bfloat16 h = __float2bfloat16(v);
    g_Weth[id] = h;
    g_Wetl[id] = __float2bfloat16(v - __bfloat162float(h));
}

// ---------------------------------------------------------------------------
// Body: one 128x128 tile of {Q,K,V} = x @ W_z. Epilogue: bf16 hi/lo splits.
// ---------------------------------------------------------------------------
__device__ void qkv_body(char* dsm, int tid, int n0, int m0, int z) {
    const uint32_t sb0 = smem_u32(dsm);
    const int lid = tid & 31, wid = tid >> 5;
    const int mw = (wid & 3) * 32, nw = (wid >> 2) * 64;

    const __nv_bfloat16* Ah = g_xh + (size_t)m0 * 512;
    const __nv_bfloat16* Al = g_xl + (size_t)m0 * 512;
    const __nv_bfloat16* Bh = g_Wth + (size_t)z * 262144 + (size_t)n0 * 512;
    const __nv_bfloat16* Bl = g_Wtl + (size_t)z * 262144 + (size_t)n0 * 512;

    float acc[2][8][4];
#pragma unroll
    for (int i = 0; i < 2; i++)
#pragma unroll
        for (int j = 0; j < 8; j++)
#pragma unroll
            for (int c = 0; c < 4; c++) acc[i][j][c] = 0.f;

#pragma unroll
    for (int t = 0; t < 2; t++) {
        const uint32_t sb = sb0 + t * BUF;
        issue_tile(sb + 0 * TBYTES, Ah + t * 32, 512, tid);
        issue_tile(sb + 1 * TBYTES, Al + t * 32, 512, tid);
        issue_tile(sb + 2 * TBYTES, Bh + t * 32, 512, tid);
        issue_tile(sb + 3 * TBYTES, Bl + t * 32, 512, tid);
        CP_COMMIT();
    }

    const int KT = 16;
    for (int kt = 0; kt < KT; kt++) {
        if (kt < KT - 1) CP_WAIT1(); else CP_WAIT0();
        __syncthreads();
        const uint32_t sb = sb0 + (kt & 1) * BUF;
        compute32(sb, sb + TBYTES, sb + 2 * TBYTES, sb + 3 * TBYTES, acc, mw, nw, lid);
        __syncthreads();
        if (kt + 2 < KT) {
            const int t = kt + 2;
            issue_tile(sb + 0 * TBYTES, Ah + t * 32, 512, tid);
            issue_tile(sb + 1 * TBYTES, Al + t * 32, 512, tid);
            issue_tile(sb + 2 * TBYTES, Bh + t * 32, 512, tid);
            issue_tile(sb + 3 * TBYTES, Bl + t * 32, 512, tid);
            CP_COMMIT();
        }
    }

    __nv_bfloat16* __restrict__ Ho = (z == 0) ? g_Qh : (z == 1) ? g_Kh : g_Vh;
    __nv_bfloat16* __restrict__ Lo = (z == 0) ? g_Ql : (z == 1) ? g_Kl : g_Vl;
#pragma unroll
    for (int mt = 0; mt < 2; mt++)
#pragma unroll
        for (int nt = 0; nt < 8; nt++) {
            const float* c = acc[mt][nt];
            const int m = m0 + mw + mt * 16 + (lid >> 2);
            const int n = n0 + nw + (nt >> 1) * 16 + (nt & 1) * 8 + (lid & 3) * 2;
            float h0 = bhi(c[0]), h1 = bhi(c[1]), h2 = bhi(c[2]), h3 = bhi(c[3]);
            *(uint32_t*)&Ho[(size_t)m * 512 + n]       = pack_bf16(h0, h1);
            *(uint32_t*)&Lo[(size_t)m * 512 + n]       = pack_bf16(c[0] - h0, c[1] - h1);
            *(uint32_t*)&Ho[(size_t)(m + 8) * 512 + n] = pack_bf16(h2, h3);
            *(uint32_t*)&Lo[(size_t)(m + 8) * 512 + n] = pack_bf16(c[2] - h2, c[3] - h3);
        }
}

// ---------------------------------------------------------------------------
// Body: one 128x128 tile of R2[bh] = Q_head @ Wet^T.  K=64.
// ---------------------------------------------------------------------------
__device__ void rel_body(char* dsm, int tid, int n0, int m0, int bh) {
    const uint32_t sb0 = smem_u32(dsm);
    const int lid = tid & 31, wid = tid >> 5;
    const int mw = (wid & 3) * 32, nw = (wid >> 2) * 64;
    const int b = bh >> 3, h = bh & 7;

    const __nv_bfloat16* Ah = g_Qh + (size_t)(b * 1024 + m0) * 512 + h * 64;
    const __nv_bfloat16* Al = g_Ql + (size_t)(b * 1024 + m0) * 512 + h * 64;
    const __nv_bfloat16* Bh = g_Weth + (size_t)n0 * 64;
    const __nv_bfloat16* Bl = g_Wetl + (size_t)n0 * 64;

    float acc[2][8][4];
#pragma unroll
    for (int i = 0; i < 2; i++)
#pragma unroll
        for (int j = 0; j < 8; j++)
#pragma unroll
            for (int c = 0; c < 4; c++) acc[i][j][c] = 0.f;

#pragma unroll
    for (int t = 0; t < 2; t++) {
        const uint32_t sb = sb0 + t * BUF;
        issue_tile(sb + 0 * TBYTES, Ah + t * 32, 512, tid);
        issue_tile(sb + 1 * TBYTES, Al + t * 32, 512, tid);
        issue_tile(sb + 2 * TBYTES, Bh + t * 32, 64, tid);
        issue_tile(sb + 3 * TBYTES, Bl + t * 32, 64, tid);
        CP_COMMIT();
    }

#pragma unroll
    for (int kt = 0; kt < 2; kt++) {
        if (kt == 0) CP_WAIT1(); else CP_WAIT0();
        __syncthreads();
        const uint32_t sb = sb0 + kt * BUF;
        compute32(sb, sb + TBYTES, sb + 2 * TBYTES, sb + 3 * TBYTES, acc, mw, nw, lid);
        __syncthreads();
    }

    float* __restrict__ C = g_R2 + (size_t)bh * 1048576;
#pragma unroll
    for (int mt = 0; mt < 2; mt++)
#pragma unroll
        for (int nt = 0; nt < 8; nt++) {
            const float* c = acc[mt][nt];
            const int m = m0 + mw + mt * 16 + (lid >> 2);
            const int n = n0 + nw + (nt >> 1) * 16 + (nt & 1) * 8 + (lid & 3) * 2;
            *(float2*)&C[(size_t)m * 1024 + n]       = make_float2(c[0], c[1]);
            *(float2*)&C[(size_t)(m + 8) * 1024 + n] = make_float2(c[2], c[3]);
        }
}

// ---------------------------------------------------------------------------
// K1a: z=0 only (produces Q splits needed by K2).
// ---------------------------------------------------------------------------
__global__ __launch_bounds__(256, 2) void k_qkv0() {
    extern __shared__ __align__(16) char dsm[];
    qkv_body(dsm, threadIdx.x, blockIdx.x * 128, blockIdx.y * 128, 0);
}

// ---------------------------------------------------------------------------
// k_mid: compacted fused launch, 3840 CTAs.
//   K1b (z=1,2): 512 tiles at id % 7 == 6 (first 512 such slots).
//   K2: 3328 LIVE tiles only (per bh: [8,7,6,5,5,6,7,8] n-tiles per m-block).
// ---------------------------------------------------------------------------
__global__ __launch_bounds__(256, 2) void k_mid() {
    extern __shared__ __align__(16) char dsm[];
    const int id = blockIdx.x;                  // [0, 3840)
    const int q = id / 7, r = id - q * 7;
    if (r == 6 && q < 512) {
        const int n0 = (q & 3) * 128;
        const int m0 = ((q >> 2) & 63) * 128;
        const int z  = 1 + (q >> 8);
        qkv_body(dsm, threadIdx.x, n0, m0, z);
    } else {
        const int k2 = id - ((q < 512) ? q : 512);   // [0, 3328) bijective
        const int bh = k2 / 52;
        const int tIdx = k2 - bh * 52;
        int mb, nb;
        if (tIdx < 8)       { mb = 0; nb = tIdx; }
        else if (tIdx < 15) { mb = 1; nb = tIdx - 8; }
        else if (tIdx < 21) { mb = 2; nb = tIdx - 15; }
        else if (tIdx < 26) { mb = 3; nb = tIdx - 21; }
        else if (tIdx < 31) { mb = 4; nb = tIdx - 26; }
        else if (tIdx < 37) { mb = 5; nb = tIdx - 31; }
        else if (tIdx < 44) { mb = 6; nb = tIdx - 37; }
        else                { mb = 7; nb = tIdx - 44; }
        rel_body(dsm, threadIdx.x, nb * 128, mb * 128, bh);
    }
}

// ---------------------------------------------------------------------------
// K3: tensorized flash attention (256 threads) with R2-gather prefetch.
// ---------------------------------------------------------------------------
static constexpr int SROW = 144;                    // 128B data + 16 pad
static constexpr int QMAT = 128 * SROW;             // 18432
static constexpr int KVMAT = 64 * SROW;             // 9216
static constexpr int KVBUF = 4 * KVMAT;             // 36864
static constexpr int SMEM_ATT = 2 * QMAT + 2 * KVBUF;   // 110592

__device__ __forceinline__ void issue_q128(uint32_t s, const __nv_bfloat16* __restrict__ g, int tid) {
#pragma unroll
    for (int i = 0; i < 4; i++) {
        int idx = tid * 4 + i;                 // 0..1023
        int row = idx >> 3, c = idx & 7;
        cp_async16(s + row * SROW + c * 16, g + (size_t)row * 512 + c * 8);
    }
}
__device__ __forceinline__ void issue_kv64(uint32_t s, const __nv_bfloat16* __restrict__ g, int tid) {
#pragma unroll
    for (int i = 0; i < 2; i++) {
        int idx = tid * 2 + i;                 // 0..511
        int row = idx >> 3, c = idx & 7;
        cp_async16(s + row * SROW + c * 16, g + (size_t)row * 512 + c * 8);
    }
}

__global__ __launch_bounds__(256) void k_attn_mma(float* __restrict__ out) {
    extern __shared__ __align__(16) char dsm[];
    const uint32_t sb = smem_u32(dsm);
    const uint32_t sQh = sb, sQl = sb + QMAT;
    const uint32_t sBuf = sb + 2 * QMAT;

    const int tid = threadIdx.x, lid = tid & 31, wid = tid >> 5;
    const int l0 = blockIdx.x * 128, h = blockIdx.y, b = blockIdx.z;

    const size_t rowoff = (size_t)(b * 1024) * 512 + h * 64;
    const __nv_bfloat16* Qhg = g_Qh + rowoff + (size_t)l0 * 512;
    const __nv_bfloat16* Qlg = g_Ql + rowoff + (size_t)l0 * 512;
    const __nv_bfloat16* Khg = g_Kh + rowoff;
    const __nv_bfloat16* Klg = g_Kl + rowoff;
    const __nv_bfloat16* Vhg = g_Vh + rowoff;
    const __nv_bfloat16* Vlg = g_Vl + rowoff;
    const float* __restrict__ R = g_R2 + (size_t)(b * 8 + h) * 1048576;

    issue_q128(sQh, Qhg, tid);
    issue_q128(sQl, Qlg, tid);
    CP_COMMIT();
#pragma unroll
    for (int t = 0; t < 2; t++) {
        const uint32_t Bt = sBuf + t * KVBUF;
        issue_kv64(Bt,             Khg + (size_t)t * 64 * 512, tid);
        issue_kv64(Bt + KVMAT,     Klg + (size_t)t * 64 * 512, tid);
        issue_kv64(Bt + 2 * KVMAT, Vhg + (size_t)t * 64 * 512, tid);
        issue_kv64(Bt + 3 * KVMAT, Vlg + (size_t)t * 64 * 512, tid);
        CP_COMMIT();
    }
    CP_WAIT2();
    __syncthreads();

    uint32_t QH[4][4], QL[4][4];
    {
        const int aoff = (16 * wid + (lid & 15)) * SROW;
#pragma unroll
        for (int ks = 0; ks < 4; ks++) {
            const int c2 = (ks * 16 + ((lid >> 4) << 3)) * 2;
            ldm_x4(QH[ks], sQh + aoff + c2);
            ldm_x4(QL[ks], sQl + aoff + c2);
        }
    }

    float O[8][4];
#pragma unroll
    for (int t = 0; t < 8; t++)
#pragma unroll
        for (int j = 0; j < 4; j++) O[t][j] = 0.f;
    float m0f = -INFINITY, m1f = -INFINITY, r0f = 0.f, r1f = 0.f;

    const int r0 = lid >> 2, c2i = (lid & 3) * 2;
    const int lA = l0 + 16 * wid + r0, lB = lA + 8;
    const float* RA = R + (size_t)lA * 1024;
    const float* RB = R + (size_t)lB * 1024;

    // ---- prefetch R2 gather for tile 0 ----
    float Rv[8][4];
#pragma unroll
    for (int t = 0; t < 8; t++) {
        const int sc = t * 8 + c2i;
        int dA0 = lA - sc;     dA0 = (dA0 < 0) ? -dA0 : dA0;
        int dA1 = lA - sc - 1; dA1 = (dA1 < 0) ? -dA1 : dA1;
        int dB0 = lB - sc;     dB0 = (dB0 < 0) ? -dB0 : dB0;
        int dB1 = lB - sc - 1; dB1 = (dB1 < 0) ? -dB1 : dB1;
        Rv[t][0] = RA[dA0]; Rv[t][1] = RA[dA1];
        Rv[t][2] = RB[dB0]; Rv[t][3] = RB[dB1];
    }

    for (int kt = 0; kt < 16; kt++) {
        if (kt < 15) CP_WAIT1(); else CP_WAIT0();
        __syncthreads();
        const uint32_t Bt = sBuf + (kt & 1) * KVBUF;
        const uint32_t bKh = Bt, bKl = Bt + KVMAT, bVh = Bt + 2 * KVMAT, bVl = Bt + 3 * KVMAT;

        float S[8][4];
#pragma unroll
        for (int t = 0; t < 8; t++)
#pragma unroll
            for (int j = 0; j < 4; j++) S[t][j] = 0.f;

#pragma unroll
        for (int ks = 0; ks < 4; ks++) {
            const int bc2 = (ks * 16 + (((lid >> 3) & 1) << 3)) * 2;
            const int br  = (lid & 7) + (((lid >> 4) & 1) << 3);
#pragma unroll
            for (int p = 0; p < 4; p++) {
                uint32_t kh[4], kl[4];
                const uint32_t boff = (p * 16 + br) * SROW + bc2;
                ldm_x4(kh, bKh + boff);
                ldm_x4(kl, bKl + boff);
                mma_bf16(S[2 * p],     QH[ks], kh[0], kh[1]);
                mma_bf16(S[2 * p + 1], QH[ks], kh[2], kh[3]);
                mma_bf16(S[2 * p],     QL[ks], kh[0], kh[1]);
                mma_bf16(S[2 * p + 1], QL[ks], kh[2], kh[3]);
                mma_bf16(S[2 * p],     QH[ks], kl[0], kl[1]);
                mma_bf16(S[2 * p + 1], QH[ks], kl[2], kl[3]);
            }
        }

        // ---- logits from prefetched Rv ----
        float mx0 = -INFINITY, mx1 = -INFINITY;
#pragma unroll
        for (int t = 0; t < 8; t++) {
            S[t][0] = 0.125f * S[t][0] * Rv[t][0];
            S[t][1] = 0.125f * S[t][1] * Rv[t][1];
            S[t][2] = 0.125f * S[t][2] * Rv[t][2];
            S[t][3] = 0.125f * S[t][3] * Rv[t][3];
            mx0 = fmaxf(mx0, fmaxf(S[t][0], S[t][1]));
            mx1 = fmaxf(mx1, fmaxf(S[t][2], S[t][3]));
        }

        // ---- prefetch Rv for tile kt+1 (hidden under softmax + PV) ----
        if (kt + 1 < 16) {
            const int sn = (kt + 1) * 64;
#pragma unroll
            for (int t = 0; t < 8; t++) {
                const int sc = sn + t * 8 + c2i;
                int dA0 = lA - sc;     dA0 = (dA0 < 0) ? -dA0 : dA0;
                int dA1 = lA - sc - 1; dA1 = (dA1 < 0) ? -dA1 : dA1;
                int dB0 = lB - sc;     dB0 = (dB0 < 0) ? -dB0 : dB0;
                int dB1 = lB - sc - 1; dB1 = (dB1 < 0) ? -dB1 : dB1;
                Rv[t][0] = RA[dA0]; Rv[t][1] = RA[dA1];
                Rv[t][2] = RB[dB0]; Rv[t][3] = RB[dB1];
            }
        }

        mx0 = fmaxf(mx0, __shfl_xor_sync(0xffffffffu, mx0, 1));
        mx0 = fmaxf(mx0, __shfl_xor_sync(0xffffffffu, mx0, 2));
        mx1 = fmaxf(mx1, __shfl_xor_sync(0xffffffffu, mx1, 1));
        mx1 = fmaxf(mx1, __shfl_xor_sync(0xffffffffu, mx1, 2));

        const float mn0 = fmaxf(m0f, mx0), mn1 = fmaxf(m1f, mx1);
        const float al0 = __expf(m0f - mn0), al1 = __expf(m1f - mn1);
        m0f = mn0; m1f = mn1;

        float sum0 = 0.f, sum1 = 0.f;
        uint32_t PH[4][4], PL[4][4];
#pragma unroll
        for (int q = 0; q < 4; q++) {
#pragma unroll
            for (int u = 0; u < 2; u++) {
                const int t = 2 * q + u;
                float e0 = __expf(S[t][0] - mn0);
                float e1 = __expf(S[t][1] - mn0);
                float e2 = __expf(S[t][2] - mn1);
                float e3 = __expf(S[t][3] - mn1);
                sum0 += e0 + e1;
                sum1 += e2 + e3;
                float h0 = bhi(e0), h1 = bhi(e1), h2 = bhi(e2), h3 = bhi(e3);
                PH[q][2 * u]     = pack_bf16(h0, h1);
                PH[q][2 * u + 1] = pack_bf16(h2, h3);
                PL[q][2 * u]     = pack_bf16(e0 - h0, e1 - h1);
                PL[q][2 * u + 1] = pack_bf16(e2 - h2, e3 - h3);
            }
        }
        sum0 += __shfl_xor_sync(0xffffffffu, sum0, 1);
        sum0 += __shfl_xor_sync(0xffffffffu, sum0, 2);
        sum1 += __shfl_xor_sync(0xffffffffu, sum1, 1);
        sum1 += __shfl_xor_sync(0xffffffffu, sum1, 2);
        r0f = r0f * al0 + sum0;
        r1f = r1f * al1 + sum1;

#pragma unroll
        for (int t = 0; t < 8; t++) {
            O[t][0] *= al0; O[t][1] *= al0;
            O[t][2] *= al1; O[t][3] *= al1;
        }

#pragma unroll
        for (int q = 0; q < 4; q++) {
            const int vr = (q * 16 + (lid & 7) + (((lid >> 3) & 1) << 3)) * SROW;
#pragma unroll
            for (int p = 0; p < 4; p++) {
                uint32_t vh[4], vl[4];
                const uint32_t voff = vr + (p * 16 + (((lid >> 4) & 1) << 3)) * 2;
                ldm_x4_t(vh, bVh + voff);
                ldm_x4_t(vl, bVl + voff);
                mma_bf16(O[2 * p],     PH[q], vh[0], vh[1]);
                mma_bf16(O[2 * p + 1], PH[q], vh[2], vh[3]);
                mma_bf16(O[2 * p],     PL[q], vh[0], vh[1]);
                mma_bf16(O[2 * p + 1], PL[q], vh[2], vh[3]);
                mma_bf16(O[2 * p],     PH[q], vl[0], vl[1]);
                mma_bf16(O[2 * p + 1], PH[q], vl[2], vl[3]);
            }
        }
        __syncthreads();

        if (kt + 2 < 16) {
            const int t = kt + 2;
            issue_kv64(Bt,             Khg + (size_t)t * 64 * 512, tid);
            issue_kv64(Bt + KVMAT,     Klg + (size_t)t * 64 * 512, tid);
            issue_kv64(Bt + 2 * KVMAT, Vhg + (size_t)t * 64 * 512, tid);
            issue_kv64(Bt + 3 * KVMAT, Vlg + (size_t)t * 64 * 512, tid);
            CP_COMMIT();
        }
    }

    const float inv0 = 1.f / r0f, inv1 = 1.f / r1f;
    float* __restrict__ oA = out + (size_t)(b * 1024 + lA) * 512 + h * 64;
    float* __restrict__ oB = out + (size_t)(b * 1024 + lB) * 512 + h * 64;
#pragma unroll
    for (int t = 0; t < 8; t++) {
        const int d = t * 8 + c2i;
        *(float2*)(oA + d) = make_float2(O[t][0] * inv0, O[t][1] * inv0);
        *(float2*)(oB + d) = make_float2(O[t][2] * inv1, O[t][3] * inv1);
    }
}

// ---------------------------------------------------------------------------

extern "C" void kernel_launch(void* const* d_in, const int* in_sizes, int n_in,
                              void* d_out, int out_size)
{
    (void)in_sizes; (void)n_in; (void)out_size;
    const float* x  = (const float*)d_in[0];
    const float* Wq = (const float*)d_in[1];
    const float* Wk = (const float*)d_in[2];
    const float* Wv = (const float*)d_in[3];
    const float* We = (const float*)d_in[4];
    float* out = (float*)d_out;

    const int SMEM_MMA = 2 * BUF;   // 81920
    cudaFuncSetAttribute(k_qkv0, cudaFuncAttributeMaxDynamicSharedMemorySize, SMEM_MMA);
    cudaFuncSetAttribute(k_mid, cudaFuncAttributeMaxDynamicSharedMemorySize, SMEM_MMA);
    cudaFuncSetAttribute(k_attn_mma, cudaFuncAttributeMaxDynamicSharedMemorySize, SMEM_ATT);

    k_split_x<<<4096, 256>>>(x);
    k_wsplit<<<dim3(16, 16, 3), dim3(32, 8)>>>(Wq, Wk, Wv);
    k_wesplit<<<256, 256>>>(We);
    k_qkv0<<<dim3(4, 64, 1), 256, SMEM_MMA>>>();
    k_mid<<<3840, 256, SMEM_MMA>>>();
    k_attn_mma<<<dim3(8, 8, 8), 256, SMEM_ATT>>>(out);
}